// round 12
// baseline (speedup 1.0000x reference)
#include <cuda_runtime.h>
#include <cuda_fp16.h>
#include <math.h>
#include <stdint.h>

#define NV    8192
#define FOUT  64
#define NP    72          // padded N: 64 feats + col64 = denominator + pad
#define JSPL  4
#define JW    (NV / JSPL) // 2048 j per CTA
#define CJ    128         // j chunk per iteration
#define NCH   (JW / CJ)   // 16 chunks

// ------------------------- device scratch (no allocs) -----------------------
__device__ __align__(128) float    g_Wh[NV * FOUT];
__device__ __align__(128) uint32_t g_adjb[NV * 256];   // bit-packed adj, 8 MB
__device__ __align__(128) __half   g_WhH[NV * NP];     // [j][72]: fp16 Wh, col64=1
__device__ __align__(128) __half   g_w1h[NV];          // fp16(-Wh1[i])
__device__ __align__(128) __half   g_w2h[NV];          // fp16(Wh2[j])
__device__ __align__(128) __half   g_b1h[NV];          // fp16(exp(Wh2[j]))
__device__ __align__(128) __half   g_b2h[NV];          // fp16(exp(0.2*Wh2[j]))
__device__ __align__(128) __half   g_rh[NV];           // fp16(exp(-0.8*Wh1[i]))
__device__ __align__(128) float    g_pnum[JSPL * NV * NP];

// ------------------------- small PTX helpers --------------------------------
__device__ __forceinline__ uint32_t smem_u32(const void* p) {
    uint32_t a;
    asm("{ .reg .u64 t; cvta.to.shared.u64 t, %1; cvt.u32.u64 %0, t; }" : "=r"(a) : "l"(p));
    return a;
}
__device__ __forceinline__ void cpa16(uint32_t dst, const void* src) {
    asm volatile("cp.async.cg.shared.global [%0], [%1], 16;" :: "r"(dst), "l"(src));
}
#define CP_COMMIT() asm volatile("cp.async.commit_group;")
#define CP_WAIT0()  asm volatile("cp.async.wait_group 0;")

__device__ __forceinline__ void ldsm4t(uint32_t* r, uint32_t addr) {
    asm volatile("ldmatrix.sync.aligned.m8n8.x4.trans.shared.b16 {%0,%1,%2,%3}, [%4];"
                 : "=r"(r[0]), "=r"(r[1]), "=r"(r[2]), "=r"(r[3]) : "r"(addr));
}
__device__ __forceinline__ void ldsm2t(uint32_t* r, uint32_t addr) {
    asm volatile("ldmatrix.sync.aligned.m8n8.x2.trans.shared.b16 {%0,%1}, [%2];"
                 : "=r"(r[0]), "=r"(r[1]) : "r"(addr));
}
__device__ __forceinline__ void mma16816(float* d, const uint32_t* a, const uint32_t* b) {
    asm volatile("mma.sync.aligned.m16n8k16.row.col.f32.f16.f16.f32 "
                 "{%0,%1,%2,%3}, {%4,%5,%6,%7}, {%8,%9}, {%0,%1,%2,%3};"
                 : "+f"(d[0]), "+f"(d[1]), "+f"(d[2]), "+f"(d[3])
                 : "r"(a[0]), "r"(a[1]), "r"(a[2]), "r"(a[3]), "r"(b[0]), "r"(b[1]));
}
__device__ __forceinline__ uint32_t hgt2_mask(uint32_t w2, uint32_t th) {
    __half2 a = *(__half2*)&w2, b = *(__half2*)&th;
    __half2 s = __hgt2(a, b);
    return *(uint32_t*)&s;
}
__device__ __forceinline__ uint32_t hmul2_u(uint32_t a, uint32_t b) {
    __half2 r = __hmul2(*(__half2*)&a, *(__half2*)&b);
    return *(uint32_t*)&r;
}
__device__ __forceinline__ uint32_t hfma2_u(uint32_t a, uint32_t b, uint32_t c) {
    __half2 r = __hfma2(*(__half2*)&a, *(__half2*)&b, *(__half2*)&c);
    return *(uint32_t*)&r;
}

// ---------------------------------------------------------------------------
// Kernel 1 (fused): blocks 0..127 -> Wh = x@W^T; blocks 128.. -> bit-pack adj
// ---------------------------------------------------------------------------
#define WH_BLOCKS   128
#define PACK_BLOCKS 2048
#define KP 68
#define SM_PRE (2 * 128 * KP * 4)

__global__ void __launch_bounds__(256) k_pre(const float* __restrict__ x,
                                             const float* __restrict__ W,
                                             const int* __restrict__ adj) {
    extern __shared__ float swh[];
    const int t = threadIdx.x;

    if (blockIdx.x < WH_BLOCKS) {
        float* xt = swh;             // [k][row]
        float* wt = swh + 128 * KP;  // [k][col]
        const int row0 = blockIdx.x * 64;

        for (int i4 = t; i4 < 2048; i4 += 256) {
            const int row = i4 >> 5, k4 = (i4 & 31) * 4;
            float4 v = ((const float4*)(x + (size_t)row0 * 128))[i4];
            xt[(k4 + 0) * KP + row] = v.x;
            xt[(k4 + 1) * KP + row] = v.y;
            xt[(k4 + 2) * KP + row] = v.z;
            xt[(k4 + 3) * KP + row] = v.w;
        }
        for (int i4 = t; i4 < 2048; i4 += 256) {
            const int col = i4 >> 5, k4 = (i4 & 31) * 4;
            float4 v = ((const float4*)W)[i4];
            wt[(k4 + 0) * KP + col] = v.x;
            wt[(k4 + 1) * KP + col] = v.y;
            wt[(k4 + 2) * KP + col] = v.z;
            wt[(k4 + 3) * KP + col] = v.w;
        }
        __syncthreads();

        const int ty = t >> 4, tx = t & 15;
        float acc[4][4];
#pragma unroll
        for (int i = 0; i < 4; i++)
#pragma unroll
            for (int j = 0; j < 4; j++) acc[i][j] = 0.f;

#pragma unroll 4
        for (int k = 0; k < 128; k++) {
            const float4 xv = *(const float4*)&xt[k * KP + ty * 4];
            const float4 wv = *(const float4*)&wt[k * KP + tx * 4];
            const float xs[4] = {xv.x, xv.y, xv.z, xv.w};
            const float ws[4] = {wv.x, wv.y, wv.z, wv.w};
#pragma unroll
            for (int i = 0; i < 4; i++)
#pragma unroll
                for (int j = 0; j < 4; j++)
                    acc[i][j] = fmaf(xs[i], ws[j], acc[i][j]);
        }
#pragma unroll
        for (int i = 0; i < 4; i++)
            *(float4*)(g_Wh + (size_t)(row0 + ty * 4 + i) * FOUT + tx * 4) =
                make_float4(acc[i][0], acc[i][1], acc[i][2], acc[i][3]);
    } else {
        // ---- pack: task = row*64 + group; group = 128 j -> 4 ballot words ----
        const int l = t & 31;
        const int wg = (blockIdx.x - WH_BLOCKS) * 8 + (t >> 5);  // 0..16383
        const int TOT_W = PACK_BLOCKS * 8;
#pragma unroll 1
        for (int it = 0; it < 32; it += 4) {
            int4 v[4];
            int rowv[4], grpv[4];
#pragma unroll
            for (int u = 0; u < 4; u++) {
                const int task = wg + (it + u) * TOT_W;
                rowv[u] = task >> 6;
                grpv[u] = task & 63;
                v[u] = __ldg((const int4*)(adj + (size_t)rowv[u] * NV + grpv[u] * 128) + l);
            }
#pragma unroll
            for (int u = 0; u < 4; u++) {
                const uint32_t b0 = __ballot_sync(0xffffffffu, v[u].x != 0);
                const uint32_t b1 = __ballot_sync(0xffffffffu, v[u].y != 0);
                const uint32_t b2 = __ballot_sync(0xffffffffu, v[u].z != 0);
                const uint32_t b3 = __ballot_sync(0xffffffffu, v[u].w != 0);
                if (l == 0) {
                    uint4 o; o.x = b0; o.y = b1; o.z = b2; o.w = b3;
                    ((uint4*)g_adjb)[(size_t)rowv[u] * 64 + grpv[u]] = o;
                }
            }
        }
    }
}

// ---------------------------------------------------------------------------
// Kernel 2: per-index scalars + fp16 Wh table [j][72] (col64 = 1)
// ---------------------------------------------------------------------------
__global__ void __launch_bounds__(128) k_prep(const float* __restrict__ a) {
    __shared__ float a_s[128];
    const int t = threadIdx.x;
    if (t < 128) a_s[t] = a[t];
    __syncthreads();

    const int j = blockIdx.x * 128 + t;
    float wh[64];
    float s1 = 0.f, s2 = 0.f;
#pragma unroll
    for (int f4 = 0; f4 < 16; f4++) {
        float4 v = ((const float4*)(g_Wh + (size_t)j * FOUT))[f4];
        wh[f4 * 4 + 0] = v.x; wh[f4 * 4 + 1] = v.y;
        wh[f4 * 4 + 2] = v.z; wh[f4 * 4 + 3] = v.w;
        s1 = fmaf(v.x, a_s[f4 * 4 + 0], s1); s2 = fmaf(v.x, a_s[64 + f4 * 4 + 0], s2);
        s1 = fmaf(v.y, a_s[f4 * 4 + 1], s1); s2 = fmaf(v.y, a_s[64 + f4 * 4 + 1], s2);
        s1 = fmaf(v.z, a_s[f4 * 4 + 2], s1); s2 = fmaf(v.z, a_s[64 + f4 * 4 + 2], s2);
        s1 = fmaf(v.w, a_s[f4 * 4 + 3], s1); s2 = fmaf(v.w, a_s[64 + f4 * 4 + 3], s2);
    }
    g_w1h[j] = __float2half(-s1);
    g_w2h[j] = __float2half(s2);
    g_b1h[j] = __float2half(expf(s2));
    g_b2h[j] = __float2half(expf(0.2f * s2));
    g_rh[j]  = __float2half(expf(-0.8f * s1));

    __half2* H = (__half2*)(g_WhH + (size_t)j * NP);
#pragma unroll
    for (int f2 = 0; f2 < 32; f2++)
        H[f2] = __floats2half2_rn(wh[f2 * 2], wh[f2 * 2 + 1]);
    H[32] = __floats2half2_rn(1.0f, 0.f);
#pragma unroll
    for (int f2 = 33; f2 < 36; f2++) H[f2] = __floats2half2_rn(0.f, 0.f);
}

// ---------------------------------------------------------------------------
// Kernel 3: main — bit-packed adj in registers, single MMA chain
// grid = 256 (64 row-blocks x 4 j-splits), 256 threads (8 warps x 16 rows)
// smem: WhH 2x18432 | scalars 2x768  = 38400 B
// ---------------------------------------------------------------------------
#define SM_WH   0
#define SM_SC   36864
#define SM_MAIN 38400

__global__ void __launch_bounds__(256, 2) k_main() {
    extern __shared__ char sm[];
    const uint32_t smb = smem_u32(sm);
    const int t = threadIdx.x;
    const int w = t >> 5, l = t & 31;
    const int rb = blockIdx.x >> 2;          // row-block 0..63
    const int js = blockIdx.x & 3;           // j-split 0..3
    const int rt0 = rb * 128;
    const int jb0 = js * JW;

    const int l2 = (l & 3) * 2;
    const int rowA = rt0 + w * 16 + (l >> 2);
    const int rowB = rowA + 8;

    // bit chunk pointers (uint4 = 128 j, ballot-interleaved)
    const uint4* bA = (const uint4*)g_adjb + (size_t)rowA * 64 + js * 16;
    const uint4* bB = (const uint4*)g_adjb + (size_t)rowB * 64 + js * 16;

    // thresholds + r factors (broadcast half2)
    const uint16_t t0 = *(const uint16_t*)&g_w1h[rowA];
    const uint16_t t1 = *(const uint16_t*)&g_w1h[rowB];
    const uint32_t th0 = (uint32_t)t0 | ((uint32_t)t0 << 16);
    const uint32_t th1 = (uint32_t)t1 | ((uint32_t)t1 << 16);
    const uint16_t r0 = *(const uint16_t*)&g_rh[rowA];
    const uint16_t r1 = *(const uint16_t*)&g_rh[rowB];
    const uint32_t rA2 = (uint32_t)r0 | ((uint32_t)r0 << 16);
    const uint32_t rB2 = (uint32_t)r1 | ((uint32_t)r1 << 16);

    const int hi = l2 >> 2;                  // 0 or 1
    const int selz = l2 & 2;                 // word select

    float acc[36];
#pragma unroll
    for (int i = 0; i < 36; i++) acc[i] = 0.f;

    auto stage = [&](int buf, int jc) {
#pragma unroll
        for (int i = 0; i < 4; i++) {
            const int idx = t + i * 256;             // 0..1023
            const int row = idx / 9, seg = idx - row * 9;
            cpa16(smb + SM_WH + buf * 18432 + row * 144 + seg * 16,
                  (const char*)g_WhH + (size_t)(jc + row) * 144 + seg * 16);
        }
        if (t < 128) {
            const int idx = 1024 + t;                // 1024..1151
            const int row = idx / 9, seg = idx - row * 9;
            cpa16(smb + SM_WH + buf * 18432 + row * 144 + seg * 16,
                  (const char*)g_WhH + (size_t)(jc + row) * 144 + seg * 16);
        } else if (t < 144) {
            cpa16(smb + SM_SC + buf * 768 + (t - 128) * 16,
                  (const char*)g_w2h + (size_t)jc * 2 + (t - 128) * 16);
        } else if (t < 160) {
            cpa16(smb + SM_SC + buf * 768 + 256 + (t - 144) * 16,
                  (const char*)g_b1h + (size_t)jc * 2 + (t - 144) * 16);
        } else if (t < 176) {
            cpa16(smb + SM_SC + buf * 768 + 512 + (t - 160) * 16,
                  (const char*)g_b2h + (size_t)jc * 2 + (t - 160) * 16);
        }
        CP_COMMIT();
    };

    stage(0, jb0);
    uint4 WA = __ldg(bA), WB = __ldg(bB);

    for (int c = 0; c < NCH; c++) {
        const int buf = c & 1;
        CP_WAIT0();
        __syncthreads();
        if (c + 1 < NCH) stage((c + 1) & 1, jb0 + (c + 1) * CJ);

        uint4 nWA, nWB;
        if (c + 1 < NCH) { nWA = __ldg(bA + c + 1); nWB = __ldg(bB + c + 1); }

        // hoisted word selection (even/odd j words for this thread)
        const uint32_t WaE = selz ? WA.z : WA.x;
        const uint32_t WaO = selz ? WA.w : WA.y;
        const uint32_t WbE = selz ? WB.z : WB.x;
        const uint32_t WbO = selz ? WB.w : WB.y;

        const uint32_t bw_base = smb + SM_WH + buf * 18432;
        const int sco = SM_SC + buf * 768;

#pragma unroll
        for (int kk = 0; kk < 8; kk++) {
            const int sh = kk * 4 + hi;
            const uint32_t s0 = WaE >> sh, s1 = WaO >> sh;
            const uint32_t u0 = WbE >> sh, u1 = WbO >> sh;
            const uint32_t MA0 = (s0 & 1u) * 0x3C00u + (s1 & 1u) * 0x3C000000u;
            const uint32_t MA1 = ((s0 >> 2) & 1u) * 0x3C00u + ((s1 >> 2) & 1u) * 0x3C000000u;
            const uint32_t MB0 = (u0 & 1u) * 0x3C00u + (u1 & 1u) * 0x3C000000u;
            const uint32_t MB1 = ((u0 >> 2) & 1u) * 0x3C00u + ((u1 >> 2) & 1u) * 0x3C000000u;

            const int klo = (kk * 16 + l2) * 2, khi = klo + 16;
            const uint32_t w2lo = *(const uint32_t*)(sm + sco + klo);
            const uint32_t w2hi = *(const uint32_t*)(sm + sco + khi);
            const uint32_t b1lo = *(const uint32_t*)(sm + sco + 256 + klo);
            const uint32_t b1hi = *(const uint32_t*)(sm + sco + 256 + khi);
            const uint32_t b2lo = *(const uint32_t*)(sm + sco + 512 + klo);
            const uint32_t b2hi = *(const uint32_t*)(sm + sco + 512 + khi);

            const uint32_t rb2loA = hmul2_u(b2lo, rA2), rb2hiA = hmul2_u(b2hi, rA2);
            const uint32_t rb2loB = hmul2_u(b2lo, rB2), rb2hiB = hmul2_u(b2hi, rB2);

            const uint32_t A0 = MA0 & hgt2_mask(w2lo, th0);
            const uint32_t A1 = MB0 & hgt2_mask(w2lo, th1);
            const uint32_t A2 = MA1 & hgt2_mask(w2hi, th0);
            const uint32_t A3 = MB1 & hgt2_mask(w2hi, th1);

            uint32_t Q[4];
            Q[0] = hfma2_u(A0 ^ MA0, rb2loA, hmul2_u(A0, b1lo));
            Q[1] = hfma2_u(A1 ^ MB0, rb2loB, hmul2_u(A1, b1lo));
            Q[2] = hfma2_u(A2 ^ MA1, rb2hiA, hmul2_u(A2, b1hi));
            Q[3] = hfma2_u(A3 ^ MB1, rb2hiB, hmul2_u(A3, b1hi));

            const int krow = kk * 16 + ((l >> 3) & 1) * 8 + (l & 7);
            const uint32_t cadd = (uint32_t)((l >> 4) * 8) * 2;

#pragma unroll
            for (int nt2 = 0; nt2 < 4; nt2++) {
                uint32_t b[4];
                const uint32_t co = (uint32_t)(nt2 * 16) * 2 + cadd;
                ldsm4t(b, bw_base + (uint32_t)krow * 144 + co);
                mma16816(acc + nt2 * 8,     Q, b);
                mma16816(acc + nt2 * 8 + 4, Q, b + 2);
            }
            {   // denominator column (col64 = 1.0)
                uint32_t b[2];
                const uint32_t a8 = (uint32_t)(kk * 16 + (l & 15)) * 144 + 128;
                ldsm2t(b, bw_base + a8);
                mma16816(acc + 32, Q, b);
            }
        }
        WA = nWA; WB = nWB;
    }

    float* baseA = g_pnum + ((size_t)js * NV + rowA) * NP;
    float* baseB = g_pnum + ((size_t)js * NV + rowB) * NP;
#pragma unroll
    for (int nt = 0; nt < 9; nt++) {
        const int col = nt * 8 + l2;
        *(float2*)(baseA + col) = make_float2(acc[nt * 4 + 0], acc[nt * 4 + 1]);
        *(float2*)(baseB + col) = make_float2(acc[nt * 4 + 2], acc[nt * 4 + 3]);
    }
}

// ---------------------------------------------------------------------------
// Kernel 4: combine j-splits, divide, elu
// ---------------------------------------------------------------------------
__global__ void __launch_bounds__(256) k_final(float* __restrict__ out) {
    const int idx = blockIdx.x * 256 + threadIdx.x;   // 8192*16 slots
    const int row = idx >> 4, f4 = idx & 15;
    float4 num = make_float4(0.f, 0.f, 0.f, 0.f);
    float den = 0.f;
#pragma unroll
    for (int js = 0; js < JSPL; js++) {
        const float* p = g_pnum + ((size_t)js * NV + row) * NP;
        const float4 v = *(const float4*)(p + f4 * 4);
        num.x += v.x; num.y += v.y; num.z += v.z; num.w += v.w;
        den += p[64];
    }
    const float inv = 1.0f / den;
    float4 o;
    float a0 = num.x * inv; o.x = a0 > 0.f ? a0 : expm1f(a0);
    float a1 = num.y * inv; o.y = a1 > 0.f ? a1 : expm1f(a1);
    float a2 = num.z * inv; o.z = a2 > 0.f ? a2 : expm1f(a2);
    float a3 = num.w * inv; o.w = a3 > 0.f ? a3 : expm1f(a3);
    *(float4*)(out + (size_t)row * FOUT + f4 * 4) = o;
}

// ---------------------------------------------------------------------------
extern "C" void kernel_launch(void* const* d_in, const int* in_sizes, int n_in,
                              void* d_out, int out_size) {
    const float* x   = (const float*)d_in[0];
    const int*   adj = (const int*)d_in[1];
    const float* W   = (const float*)d_in[2];
    const float* a   = (const float*)d_in[3];
    float* out = (float*)d_out;

    cudaFuncSetAttribute(k_pre,  cudaFuncAttributeMaxDynamicSharedMemorySize, SM_PRE);
    cudaFuncSetAttribute(k_main, cudaFuncAttributeMaxDynamicSharedMemorySize, SM_MAIN);

    k_pre<<<WH_BLOCKS + PACK_BLOCKS, 256, SM_PRE>>>(x, W, adj);
    k_prep<<<NV / 128, 128>>>(a);
    k_main<<<256, 256, SM_MAIN>>>();
    k_final<<<NV * 16 / 256, 256>>>(out);
}

// round 15
// speedup vs baseline: 1.2875x; 1.2875x over previous
#include <cuda_runtime.h>
#include <cuda_fp16.h>
#include <math.h>
#include <stdint.h>

#define NV    8192
#define FOUT  64
#define NP    72          // padded N: 64 feats + col64 = denominator + pad
#define JSPL  8
#define JW    (NV / JSPL) // 1024 j per CTA
#define CJ    32          // j chunk staged in smem
#define NCH   (JW / CJ)   // 32 chunks
#define RCTA  256         // rows per CTA (8 warps x 32 rows)

// ------------------------- device scratch (no allocs) -----------------------
__device__ __align__(128) float  g_Wh[NV * FOUT];
__device__ __align__(128) __half g_WhH[NV * NP];   // [j][72]: fp16 Wh, col64=1
__device__ __align__(128) __half g_w1h[NV];        // fp16(-Wh1[i])
__device__ __align__(128) __half g_w2h[NV];        // fp16(Wh2[j])
__device__ __align__(128) __half g_b1h[NV];        // fp16(exp(Wh2[j]))
__device__ __align__(128) __half g_b2h[NV];        // fp16(exp(0.2*Wh2[j]))
__device__ __align__(128) __half g_rh[NV];         // fp16(exp(-0.8*Wh1[i]))
__device__ __align__(128) float  g_pnum[JSPL * NV * NP];

// ------------------------- small PTX helpers --------------------------------
__device__ __forceinline__ uint32_t smem_u32(const void* p) {
    uint32_t a;
    asm("{ .reg .u64 t; cvta.to.shared.u64 t, %1; cvt.u32.u64 %0, t; }" : "=r"(a) : "l"(p));
    return a;
}
__device__ __forceinline__ void cpa16(uint32_t dst, const void* src) {
    asm volatile("cp.async.cg.shared.global [%0], [%1], 16;" :: "r"(dst), "l"(src));
}
#define CP_COMMIT() asm volatile("cp.async.commit_group;")
#define CP_WAIT0()  asm volatile("cp.async.wait_group 0;")

__device__ __forceinline__ void ldsm4t(uint32_t* r, uint32_t addr) {
    asm volatile("ldmatrix.sync.aligned.m8n8.x4.trans.shared.b16 {%0,%1,%2,%3}, [%4];"
                 : "=r"(r[0]), "=r"(r[1]), "=r"(r[2]), "=r"(r[3]) : "r"(addr));
}
__device__ __forceinline__ void ldsm2t(uint32_t* r, uint32_t addr) {
    asm volatile("ldmatrix.sync.aligned.m8n8.x2.trans.shared.b16 {%0,%1}, [%2];"
                 : "=r"(r[0]), "=r"(r[1]) : "r"(addr));
}
__device__ __forceinline__ void mma16816(float* d, const uint32_t* a, const uint32_t* b) {
    asm volatile("mma.sync.aligned.m16n8k16.row.col.f32.f16.f16.f32 "
                 "{%0,%1,%2,%3}, {%4,%5,%6,%7}, {%8,%9}, {%0,%1,%2,%3};"
                 : "+f"(d[0]), "+f"(d[1]), "+f"(d[2]), "+f"(d[3])
                 : "r"(a[0]), "r"(a[1]), "r"(a[2]), "r"(a[3]), "r"(b[0]), "r"(b[1]));
}
__device__ __forceinline__ uint32_t hgt2_mask(uint32_t w2, uint32_t th) {
    __half2 a = *(__half2*)&w2, b = *(__half2*)&th;
    __half2 s = __hgt2(a, b);
    return *(uint32_t*)&s;
}
__device__ __forceinline__ uint32_t hmul2_u(uint32_t a, uint32_t b) {
    __half2 r = __hmul2(*(__half2*)&a, *(__half2*)&b);
    return *(uint32_t*)&r;
}
__device__ __forceinline__ uint32_t hfma2_u(uint32_t a, uint32_t b, uint32_t c) {
    __half2 r = __hfma2(*(__half2*)&a, *(__half2*)&b, *(__half2*)&c);
    return *(uint32_t*)&r;
}

// ---------------------------------------------------------------------------
// Kernel 1: Wh = x @ W^T   (fp32, 4x4 register tile over k-major smem)
// ---------------------------------------------------------------------------
#define KP 68
#define SM_WHK (2 * 128 * KP * 4)
__global__ void __launch_bounds__(256) k_wh(const float* __restrict__ x,
                                            const float* __restrict__ W) {
    extern __shared__ float swh[];
    float* xt = swh;
    float* wt = swh + 128 * KP;
    const int t = threadIdx.x;
    const int row0 = blockIdx.x * 64;

    for (int i4 = t; i4 < 2048; i4 += 256) {
        const int row = i4 >> 5, k4 = (i4 & 31) * 4;
        float4 v = ((const float4*)(x + (size_t)row0 * 128))[i4];
        xt[(k4 + 0) * KP + row] = v.x;
        xt[(k4 + 1) * KP + row] = v.y;
        xt[(k4 + 2) * KP + row] = v.z;
        xt[(k4 + 3) * KP + row] = v.w;
    }
    for (int i4 = t; i4 < 2048; i4 += 256) {
        const int col = i4 >> 5, k4 = (i4 & 31) * 4;
        float4 v = ((const float4*)W)[i4];
        wt[(k4 + 0) * KP + col] = v.x;
        wt[(k4 + 1) * KP + col] = v.y;
        wt[(k4 + 2) * KP + col] = v.z;
        wt[(k4 + 3) * KP + col] = v.w;
    }
    __syncthreads();

    const int ty = t >> 4, tx = t & 15;
    float acc[4][4];
#pragma unroll
    for (int i = 0; i < 4; i++)
#pragma unroll
        for (int j = 0; j < 4; j++) acc[i][j] = 0.f;

#pragma unroll 4
    for (int k = 0; k < 128; k++) {
        const float4 xv = *(const float4*)&xt[k * KP + ty * 4];
        const float4 wv = *(const float4*)&wt[k * KP + tx * 4];
        const float xs[4] = {xv.x, xv.y, xv.z, xv.w};
        const float ws[4] = {wv.x, wv.y, wv.z, wv.w};
#pragma unroll
        for (int i = 0; i < 4; i++)
#pragma unroll
            for (int j = 0; j < 4; j++)
                acc[i][j] = fmaf(xs[i], ws[j], acc[i][j]);
    }
#pragma unroll
    for (int i = 0; i < 4; i++)
        *(float4*)(g_Wh + (size_t)(row0 + ty * 4 + i) * FOUT + tx * 4) =
            make_float4(acc[i][0], acc[i][1], acc[i][2], acc[i][3]);
}

// ---------------------------------------------------------------------------
// Kernel 2: per-index scalars + fp16 Wh table [j][72] (col64 = 1)
// ---------------------------------------------------------------------------
__global__ void __launch_bounds__(128) k_prep(const float* __restrict__ a) {
    __shared__ float a_s[128];
    const int t = threadIdx.x;
    if (t < 128) a_s[t] = a[t];
    __syncthreads();

    const int j = blockIdx.x * 128 + t;
    float wh[64];
    float s1 = 0.f, s2 = 0.f;
#pragma unroll
    for (int f4 = 0; f4 < 16; f4++) {
        float4 v = ((const float4*)(g_Wh + (size_t)j * FOUT))[f4];
        wh[f4 * 4 + 0] = v.x; wh[f4 * 4 + 1] = v.y;
        wh[f4 * 4 + 2] = v.z; wh[f4 * 4 + 3] = v.w;
        s1 = fmaf(v.x, a_s[f4 * 4 + 0], s1); s2 = fmaf(v.x, a_s[64 + f4 * 4 + 0], s2);
        s1 = fmaf(v.y, a_s[f4 * 4 + 1], s1); s2 = fmaf(v.y, a_s[64 + f4 * 4 + 1], s2);
        s1 = fmaf(v.z, a_s[f4 * 4 + 2], s1); s2 = fmaf(v.z, a_s[64 + f4 * 4 + 2], s2);
        s1 = fmaf(v.w, a_s[f4 * 4 + 3], s1); s2 = fmaf(v.w, a_s[64 + f4 * 4 + 3], s2);
    }
    g_w1h[j] = __float2half(-s1);
    g_w2h[j] = __float2half(s2);
    g_b1h[j] = __float2half(expf(s2));
    g_b2h[j] = __float2half(expf(0.2f * s2));
    g_rh[j]  = __float2half(expf(-0.8f * s1));

    __half2* H = (__half2*)(g_WhH + (size_t)j * NP);
#pragma unroll
    for (int f2 = 0; f2 < 32; f2++)
        H[f2] = __floats2half2_rn(wh[f2 * 2], wh[f2 * 2 + 1]);
    H[32] = __floats2half2_rn(1.0f, 0.f);
#pragma unroll
    for (int f2 = 33; f2 < 36; f2++) H[f2] = __floats2half2_rn(0.f, 0.f);
}

// ---------------------------------------------------------------------------
// Kernel 3: main — 32 rows/warp (2 A-frags per B-frag load), adj via cp.async
// grid = 256 (32 row-blocks x 8 j-splits), 256 threads (8 warps x 32 rows)
// smem: adj 2x36864 | WhH 2x4608 | scalars 2x192  = 83328 B
// ---------------------------------------------------------------------------
#define APITCH  144                     // 32 ints (128B) + 16B pad
#define SM_ADJ  0                       // 2 x 36864 = 73728
#define SM_WH   73728                   // 2 x 4608  = 9216
#define SM_SC   82944                   // 2 x 192  (w2 | +64 b1 | +128 b2)
#define SM_MAIN 83328

__global__ void __launch_bounds__(256, 2) k_main(const int* __restrict__ adj) {
    extern __shared__ char sm[];
    const uint32_t smb = smem_u32(sm);
    const int t = threadIdx.x;
    const int w = t >> 5, l = t & 31;
    const int rb = blockIdx.x >> 3;          // row-block 0..31
    const int js = blockIdx.x & 7;           // j-split 0..7
    const int rt0 = rb * RCTA;
    const int jb0 = js * JW;

    const int l2 = (l & 3) * 2;
    const int rl0 = w * 32 + (l >> 2);       // local row stream base
    const int rowA = rt0 + rl0,      rowB = rowA + 8;
    const int rowC = rowA + 16,      rowD = rowA + 24;

    // thresholds + r factors (broadcast half2) for 4 row streams
    uint32_t th[4], rr[4];
    {
        const int rws[4] = {rowA, rowB, rowC, rowD};
#pragma unroll
        for (int i = 0; i < 4; i++) {
            const uint16_t tv = *(const uint16_t*)&g_w1h[rws[i]];
            const uint16_t rv = *(const uint16_t*)&g_rh[rws[i]];
            th[i] = (uint32_t)tv | ((uint32_t)tv << 16);
            rr[i] = (uint32_t)rv | ((uint32_t)rv << 16);
        }
    }

    float acc1[36], acc2[36];
#pragma unroll
    for (int i = 0; i < 36; i++) { acc1[i] = 0.f; acc2[i] = 0.f; }

    // ---- staging: chunk at global j = jc, into buffer buf ----
    auto stage = [&](int buf, int jc) {
        const char* asrc = (const char*)(adj + (size_t)rt0 * NV + jc);
        const uint32_t adst = smb + SM_ADJ + buf * 36864;
#pragma unroll
        for (int i = 0; i < 8; i++) {
            const int idx = t + i * 256;             // 0..2047 (256 rows x 8 seg)
            const int row = idx >> 3, seg = idx & 7;
            cpa16(adst + row * APITCH + seg * 16,
                  asrc + (size_t)row * (NV * 4) + seg * 16);
        }
        {   // WhH: 32 rows x 9 segs = 288 tasks (256 threads -> 1 + low-32 extra)
            const int row = t / 9, seg = t - row * 9;
            cpa16(smb + SM_WH + buf * 4608 + row * 144 + seg * 16,
                  (const char*)g_WhH + (size_t)(jc + row) * 144 + seg * 16);
            if (t < 32) {
                const int idx = 256 + t;
                const int row2 = idx / 9, seg2 = idx - row2 * 9;
                cpa16(smb + SM_WH + buf * 4608 + row2 * 144 + seg2 * 16,
                      (const char*)g_WhH + (size_t)(jc + row2) * 144 + seg2 * 16);
            }
        }
        if (t >= 128 && t < 132)
            cpa16(smb + SM_SC + buf * 192 + (t - 128) * 16,
                  (const char*)g_w2h + (size_t)jc * 2 + (t - 128) * 16);
        else if (t >= 132 && t < 136)
            cpa16(smb + SM_SC + buf * 192 + 64 + (t - 132) * 16,
                  (const char*)g_b1h + (size_t)jc * 2 + (t - 132) * 16);
        else if (t >= 136 && t < 140)
            cpa16(smb + SM_SC + buf * 192 + 128 + (t - 136) * 16,
                  (const char*)g_b2h + (size_t)jc * 2 + (t - 136) * 16);
        CP_COMMIT();
    };

    stage(0, jb0);

    for (int c = 0; c < NCH; c++) {
        const int buf = c & 1;
        CP_WAIT0();
        __syncthreads();
        if (c + 1 < NCH) stage((c + 1) & 1, jb0 + (c + 1) * CJ);

        const int ao = SM_ADJ + buf * 36864;
        const uint32_t bw_base = smb + SM_WH + buf * 4608;
        const int sco = SM_SC + buf * 192;

#pragma unroll
        for (int kk = 0; kk < 2; kk++) {
            const int jbyte = (kk * 16 + l2) * 4;
            const int2 mA0 = *(const int2*)(sm + ao + (rl0     ) * APITCH + jbyte);
            const int2 mA1 = *(const int2*)(sm + ao + (rl0     ) * APITCH + jbyte + 32);
            const int2 mB0 = *(const int2*)(sm + ao + (rl0 +  8) * APITCH + jbyte);
            const int2 mB1 = *(const int2*)(sm + ao + (rl0 +  8) * APITCH + jbyte + 32);
            const int2 mC0 = *(const int2*)(sm + ao + (rl0 + 16) * APITCH + jbyte);
            const int2 mC1 = *(const int2*)(sm + ao + (rl0 + 16) * APITCH + jbyte + 32);
            const int2 mD0 = *(const int2*)(sm + ao + (rl0 + 24) * APITCH + jbyte);
            const int2 mD1 = *(const int2*)(sm + ao + (rl0 + 24) * APITCH + jbyte + 32);

            const int klo = (kk * 16 + l2) * 2, khi = klo + 16;
            const uint32_t w2lo = *(const uint32_t*)(sm + sco + klo);
            const uint32_t w2hi = *(const uint32_t*)(sm + sco + khi);
            const uint32_t b1lo = *(const uint32_t*)(sm + sco + 64 + klo);
            const uint32_t b1hi = *(const uint32_t*)(sm + sco + 64 + khi);
            const uint32_t b2lo = *(const uint32_t*)(sm + sco + 128 + klo);
            const uint32_t b2hi = *(const uint32_t*)(sm + sco + 128 + khi);

            uint32_t Q1[4], Q2[4];
            {
                const int2 mlo[4] = {mA0, mB0, mC0, mD0};
                const int2 mhi[4] = {mA1, mB1, mC1, mD1};
                uint32_t q[8];
#pragma unroll
                for (int i = 0; i < 4; i++) {
                    const uint32_t Mlo = (uint32_t)mlo[i].x * 0x3C00u + (uint32_t)mlo[i].y * 0x3C000000u;
                    const uint32_t Mhi = (uint32_t)mhi[i].x * 0x3C00u + (uint32_t)mhi[i].y * 0x3C000000u;
                    const uint32_t Alo = Mlo & hgt2_mask(w2lo, th[i]);
                    const uint32_t Ahi = Mhi & hgt2_mask(w2hi, th[i]);
                    q[i * 2 + 0] = hfma2_u(Alo ^ Mlo, hmul2_u(b2lo, rr[i]), hmul2_u(Alo, b1lo));
                    q[i * 2 + 1] = hfma2_u(Ahi ^ Mhi, hmul2_u(b2hi, rr[i]), hmul2_u(Ahi, b1hi));
                }
                Q1[0] = q[0]; Q1[1] = q[2]; Q1[2] = q[1]; Q1[3] = q[3];
                Q2[0] = q[4]; Q2[1] = q[6]; Q2[2] = q[5]; Q2[3] = q[7];
            }

            const int krow = kk * 16 + ((l >> 3) & 1) * 8 + (l & 7);
            const uint32_t cadd = (uint32_t)((l >> 4) * 8) * 2;

#pragma unroll
            for (int nt2 = 0; nt2 < 4; nt2++) {
                uint32_t b[4];
                const uint32_t co = (uint32_t)(nt2 * 16) * 2 + cadd;
                ldsm4t(b, bw_base + (uint32_t)krow * 144 + co);
                mma16816(acc1 + nt2 * 8,     Q1, b);
                mma16816(acc1 + nt2 * 8 + 4, Q1, b + 2);
                mma16816(acc2 + nt2 * 8,     Q2, b);
                mma16816(acc2 + nt2 * 8 + 4, Q2, b + 2);
            }
            {   // denominator column (col64 = 1.0)
                uint32_t b[2];
                const uint32_t a8 = (uint32_t)(kk * 16 + (l & 15)) * 144 + 128;
                ldsm2t(b, bw_base + a8);
                mma16816(acc1 + 32, Q1, b);
                mma16816(acc2 + 32, Q2, b);
            }
        }
        __syncthreads();
    }

    // epilogue: write partials (col64 = denominator)
    float* baseA = g_pnum + ((size_t)js * NV + rowA) * NP;
    float* baseB = g_pnum + ((size_t)js * NV + rowB) * NP;
    float* baseC = g_pnum + ((size_t)js * NV + rowC) * NP;
    float* baseD = g_pnum + ((size_t)js * NV + rowD) * NP;
#pragma unroll
    for (int nt = 0; nt < 9; nt++) {
        const int col = nt * 8 + l2;
        *(float2*)(baseA + col) = make_float2(acc1[nt * 4 + 0], acc1[nt * 4 + 1]);
        *(float2*)(baseB + col) = make_float2(acc1[nt * 4 + 2], acc1[nt * 4 + 3]);
        *(float2*)(baseC + col) = make_float2(acc2[nt * 4 + 0], acc2[nt * 4 + 1]);
        *(float2*)(baseD + col) = make_float2(acc2[nt * 4 + 2], acc2[nt * 4 + 3]);
    }
}

// ---------------------------------------------------------------------------
// Kernel 4: combine j-splits, divide, elu
// ---------------------------------------------------------------------------
__global__ void __launch_bounds__(256) k_final(float* __restrict__ out) {
    const int idx = blockIdx.x * 256 + threadIdx.x;   // 8192*16 slots
    const int row = idx >> 4, f4 = idx & 15;
    float4 num = make_float4(0.f, 0.f, 0.f, 0.f);
    float den = 0.f;
#pragma unroll
    for (int js = 0; js < JSPL; js++) {
        const float* p = g_pnum + ((size_t)js * NV + row) * NP;
        const float4 v = *(const float4*)(p + f4 * 4);
        num.x += v.x; num.y += v.y; num.z += v.z; num.w += v.w;
        den += p[64];
    }
    const float inv = 1.0f / den;
    float4 o;
    float a0 = num.x * inv; o.x = a0 > 0.f ? a0 : expm1f(a0);
    float a1 = num.y * inv; o.y = a1 > 0.f ? a1 : expm1f(a1);
    float a2 = num.z * inv; o.z = a2 > 0.f ? a2 : expm1f(a2);
    float a3 = num.w * inv; o.w = a3 > 0.f ? a3 : expm1f(a3);
    *(float4*)(out + (size_t)row * FOUT + f4 * 4) = o;
}

// ---------------------------------------------------------------------------
extern "C" void kernel_launch(void* const* d_in, const int* in_sizes, int n_in,
                              void* d_out, int out_size) {
    const float* x   = (const float*)d_in[0];
    const int*   adj = (const int*)d_in[1];
    const float* W   = (const float*)d_in[2];
    const float* a   = (const float*)d_in[3];
    float* out = (float*)d_out;

    cudaFuncSetAttribute(k_wh,   cudaFuncAttributeMaxDynamicSharedMemorySize, SM_WHK);
    cudaFuncSetAttribute(k_main, cudaFuncAttributeMaxDynamicSharedMemorySize, SM_MAIN);

    k_wh<<<NV / 64, 256, SM_WHK>>>(x, W);
    k_prep<<<NV / 128, 128>>>(a);
    k_main<<<256, 256, SM_MAIN>>>(adj);
    k_final<<<NV * 16 / 256, 256>>>(out);
}